// round 13
// baseline (speedup 1.0000x reference)
#include <cuda_runtime.h>
#include <cstdint>

#define N_ROWS  16384
#define D       2048
#define ETA     0.01f
#define GRID1   148
#define THREADS 256
#define RPS     8                   // rows per pipeline stage
#define NSTAGE  3
#define SWEEP   (GRID1 * RPS)       // 1184 rows per sweep
#define STAGE_FLOATS (RPS * D)      // 16384 floats = 64 KB
#define STAGE_BYTES  (STAGE_FLOATS * 4)
#define ROW_BYTES    (D * 4)        // 8 KB

// Per-CTA partials: 148 x 2048 floats (1.2 MB)
__device__ float g_partial[GRID1][D];

// ---- mbarrier + bulk-copy primitives --------------------------------------
__device__ __forceinline__ uint32_t smem_u32(const void* p) {
    return (uint32_t)__cvta_generic_to_shared(p);
}
__device__ __forceinline__ void mbar_init(uint32_t mbar, uint32_t count) {
    asm volatile("mbarrier.init.shared.b64 [%0], %1;" :: "r"(mbar), "r"(count) : "memory");
}
__device__ __forceinline__ void mbar_expect_tx(uint32_t mbar, uint32_t bytes) {
    asm volatile("mbarrier.arrive.expect_tx.shared.b64 _, [%0], %1;"
                 :: "r"(mbar), "r"(bytes) : "memory");
}
__device__ __forceinline__ void mbar_wait(uint32_t mbar, uint32_t phase) {
    asm volatile(
        "{\n\t"
        ".reg .pred P;\n\t"
        "WAIT_%=:\n\t"
        "mbarrier.try_wait.parity.acquire.cta.shared::cta.b64 P, [%0], %1, 0x989680;\n\t"
        "@!P bra WAIT_%=;\n\t"
        "}"
        :: "r"(mbar), "r"(phase) : "memory");
}
__device__ __forceinline__ void bulk_copy(uint32_t smem_dst, const void* gsrc,
                                          uint32_t bytes, uint32_t mbar) {
    asm volatile(
        "cp.async.bulk.shared::cta.global.mbarrier::complete_tx::bytes "
        "[%0], [%1], %2, [%3];"
        :: "r"(smem_dst), "l"(gsrc), "r"(bytes), "r"(mbar) : "memory");
}

// pass1: TMA-staged pipeline (R12) + EARLY REFILL (slot reissued right after
// the register-load barrier, one compute-phase earlier) + parity-buffered
// s_dot/s_c so no barrier trails the accumulate.
__global__ __launch_bounds__(THREADS, 1)
void pass1_kernel(const float* __restrict__ theta,
                  const float* __restrict__ xs)
{
    extern __shared__ float buf[];              // NSTAGE * 64 KB
    __shared__ __align__(8) unsigned long long mbar_full[NSTAGE];
    __shared__ float s_dot[2][8][RPS];          // parity-indexed
    __shared__ float s_c[2][RPS];

    const int t    = threadIdx.x;
    const int wid  = t >> 5;
    const int lane = t & 31;

    const float4 th0 = *reinterpret_cast<const float4*>(theta + 4 * t);
    const float4 th1 = *reinterpret_cast<const float4*>(theta + 1024 + 4 * t);

    float4 acc0 = make_float4(0.f, 0.f, 0.f, 0.f);
    float4 acc1 = make_float4(0.f, 0.f, 0.f, 0.f);

    const int first = blockIdx.x * RPS;
    const int nst   = (N_ROWS - first + SWEEP - 1) / SWEEP;   // 13 or 14

    if (t == 0) {
        #pragma unroll
        for (int i = 0; i < NSTAGE; i++)
            mbar_init(smem_u32(&mbar_full[i]), 1);
    }
    __syncthreads();

    auto issue = [&](int s) {
        const int slot = s % NSTAGE;
        const uint32_t mbar = smem_u32(&mbar_full[slot]);
        const uint32_t dst0 = smem_u32(buf + slot * STAGE_FLOATS);
        const int base = first + s * SWEEP;
        mbar_expect_tx(mbar, STAGE_BYTES);
        #pragma unroll
        for (int j = 0; j < RPS; j++) {
            int rj = base + j;
            if (rj > N_ROWS - 1) rj = N_ROWS - 1;   // clamp; c forced to 0 later
            bulk_copy(dst0 + j * ROW_BYTES, xs + (size_t)rj * D, ROW_BYTES, mbar);
        }
    };

    if (t == 0) {
        #pragma unroll
        for (int s = 0; s < NSTAGE; s++)
            if (s < nst) issue(s);
    }

    for (int s = 0; s < nst; s++) {
        const int slot = s % NSTAGE;
        const int p    = s & 1;
        mbar_wait(smem_u32(&mbar_full[slot]), (uint32_t)((s / NSTAGE) & 1));

        const float* src = buf + slot * STAGE_FLOATS;
        float4 a[RPS][2];
        float  sm[RPS];

        #pragma unroll
        for (int j = 0; j < RPS; j++) {
            a[j][0] = *reinterpret_cast<const float4*>(src + j * D + 4 * t);
            a[j][1] = *reinterpret_cast<const float4*>(src + j * D + 1024 + 4 * t);
            sm[j] = a[j][0].x * th0.x + a[j][0].y * th0.y
                  + a[j][0].z * th0.z + a[j][0].w * th0.w
                  + a[j][1].x * th1.x + a[j][1].y * th1.y
                  + a[j][1].z * th1.z + a[j][1].w * th1.w;
        }
        __syncthreads();                    // BAR_a: all warps done reading slot
                                            // (also orders parity reuse below)
        {
            const int sn = s + NSTAGE;
            if (sn < nst && t == 0) issue(sn);   // EARLY refill of freed slot
        }

        #pragma unroll
        for (int o = 16; o > 0; o >>= 1) {
            #pragma unroll
            for (int j = 0; j < RPS; j++)
                sm[j] += __shfl_down_sync(0xffffffffu, sm[j], o);
        }
        if (lane == 0) {
            #pragma unroll
            for (int j = 0; j < RPS; j++)
                s_dot[p][wid][j] = sm[j];
        }
        __syncthreads();                    // BAR_b: s_dot visible

        if (t < RPS) {
            float v = s_dot[p][0][t];
            #pragma unroll
            for (int w = 1; w < 8; w++) v += s_dot[p][w][t];
            const int rj = first + s * SWEEP + t;
            s_c[p][t] = (rj < N_ROWS) ? (ETA / (1.0f + __expf(v))) : 0.f;
        }
        __syncthreads();                    // BAR_c: s_c visible

        #pragma unroll
        for (int j = 0; j < RPS; j++) {
            const float c = s_c[p][j];
            acc0.x += c * a[j][0].x;  acc0.y += c * a[j][0].y;
            acc0.z += c * a[j][0].z;  acc0.w += c * a[j][0].w;
            acc1.x += c * a[j][1].x;  acc1.y += c * a[j][1].y;
            acc1.z += c * a[j][1].z;  acc1.w += c * a[j][1].w;
        }
        // no trailing barrier: next stage writes parity p^1, ordered by its BAR_a
    }

    float* part = g_partial[blockIdx.x];
    *reinterpret_cast<float4*>(part + 4 * t)        = acc0;
    *reinterpret_cast<float4*>(part + 1024 + 4 * t) = acc1;
}

// Fused reduction: 148 partials + theta -> out. grid 16 x 512 (R11 shape).
__global__ __launch_bounds__(512)
void pass2_kernel(const float* __restrict__ theta,
                  float* __restrict__ out)
{
    __shared__ float4 s_red[16][32];

    const int lane32 = threadIdx.x & 31;
    const int grp    = threadIdx.x >> 5;
    const int col4   = blockIdx.x * 32 + lane32;

    // 148 = 4*10 + 12*9: grp < 4 have 10 rows, others 9.
    const int start = grp * 9 + (grp < 4 ? grp : 4);
    const int count = 9 + (grp < 4 ? 1 : 0);

    float4 acc[5];
    #pragma unroll
    for (int k = 0; k < 5; k++) acc[k] = make_float4(0.f, 0.f, 0.f, 0.f);

    #pragma unroll 5
    for (int k = 0; k < 5; k++) {
        const float4 v = reinterpret_cast<const float4*>(g_partial[start + k])[col4];
        acc[k].x += v.x; acc[k].y += v.y; acc[k].z += v.z; acc[k].w += v.w;
    }
    #pragma unroll 5
    for (int k = 0; k < 5; k++) {
        if (5 + k < count) {
            const float4 v = reinterpret_cast<const float4*>(g_partial[start + 5 + k])[col4];
            acc[k].x += v.x; acc[k].y += v.y; acc[k].z += v.z; acc[k].w += v.w;
        }
    }

    float4 s;
    s.x = ((acc[0].x + acc[1].x) + (acc[2].x + acc[3].x)) + acc[4].x;
    s.y = ((acc[0].y + acc[1].y) + (acc[2].y + acc[3].y)) + acc[4].y;
    s.z = ((acc[0].z + acc[1].z) + (acc[2].z + acc[3].z)) + acc[4].z;
    s.w = ((acc[0].w + acc[1].w) + (acc[2].w + acc[3].w)) + acc[4].w;

    s_red[grp][lane32] = s;
    __syncthreads();

    if (grp == 0) {
        const float4 th = reinterpret_cast<const float4*>(theta)[col4];
        float4 r = th;
        #pragma unroll
        for (int g = 0; g < 16; g++) {
            const float4 v = s_red[g][lane32];
            r.x += v.x; r.y += v.y; r.z += v.z; r.w += v.w;
        }
        reinterpret_cast<float4*>(out)[col4] = r;
    }
}

extern "C" void kernel_launch(void* const* d_in, const int* in_sizes, int n_in,
                              void* d_out, int out_size)
{
    const float* theta = (const float*)d_in[0];
    const float* xs    = (const float*)d_in[1];
    if (n_in >= 2 && in_sizes[0] > in_sizes[1]) {
        theta = (const float*)d_in[1];
        xs    = (const float*)d_in[0];
    }
    float* out = (float*)d_out;

    const int smem = NSTAGE * STAGE_BYTES;   // 196608
    cudaFuncSetAttribute(pass1_kernel,
                         cudaFuncAttributeMaxDynamicSharedMemorySize, smem);

    pass1_kernel<<<GRID1, THREADS, smem>>>(theta, xs);
    pass2_kernel<<<16, 512>>>(theta, out);
}

// round 15
// speedup vs baseline: 1.1075x; 1.1075x over previous
#include <cuda_runtime.h>
#include <cstdint>

#define N_ROWS  16384
#define D       2048
#define ETA     0.01f
#define GRID1   148
#define THREADS 256
#define RPS     6                   // rows per pipeline stage
#define NSTAGE  4
#define SWEEP   (GRID1 * RPS)       // 888 rows per sweep
#define STAGE_FLOATS (RPS * D)      // 12288 floats = 48 KB
#define STAGE_BYTES  (STAGE_FLOATS * 4)
#define ROW_BYTES    (D * 4)        // 8 KB

// Per-CTA partials: 148 x 2048 floats (1.2 MB)
__device__ float g_partial[GRID1][D];

// ---- mbarrier + bulk-copy primitives --------------------------------------
__device__ __forceinline__ uint32_t smem_u32(const void* p) {
    return (uint32_t)__cvta_generic_to_shared(p);
}
__device__ __forceinline__ void mbar_init(uint32_t mbar, uint32_t count) {
    asm volatile("mbarrier.init.shared.b64 [%0], %1;" :: "r"(mbar), "r"(count) : "memory");
}
__device__ __forceinline__ void mbar_expect_tx(uint32_t mbar, uint32_t bytes) {
    asm volatile("mbarrier.arrive.expect_tx.shared.b64 _, [%0], %1;"
                 :: "r"(mbar), "r"(bytes) : "memory");
}
__device__ __forceinline__ void mbar_wait(uint32_t mbar, uint32_t phase) {
    asm volatile(
        "{\n\t"
        ".reg .pred P;\n\t"
        "WAIT_%=:\n\t"
        "mbarrier.try_wait.parity.acquire.cta.shared::cta.b64 P, [%0], %1, 0x989680;\n\t"
        "@!P bra WAIT_%=;\n\t"
        "}"
        :: "r"(mbar), "r"(phase) : "memory");
}
__device__ __forceinline__ void bulk_copy(uint32_t smem_dst, const void* gsrc,
                                          uint32_t bytes, uint32_t mbar) {
    asm volatile(
        "cp.async.bulk.shared::cta.global.mbarrier::complete_tx::bytes "
        "[%0], [%1], %2, [%3];"
        :: "r"(smem_dst), "l"(gsrc), "r"(bytes), "r"(mbar) : "memory");
}

// pass1: R12 structure (TMA stage loads, LATE refill at end of stage loop),
// pipeline deepened to 4 x 48 KB stages (same 192 KB total).
__global__ __launch_bounds__(THREADS, 1)
void pass1_kernel(const float* __restrict__ theta,
                  const float* __restrict__ xs)
{
    extern __shared__ float buf[];              // NSTAGE * 48 KB
    __shared__ __align__(8) unsigned long long mbar_full[NSTAGE];
    __shared__ float s_dot[8][RPS];
    __shared__ float s_c[RPS];

    const int t    = threadIdx.x;
    const int wid  = t >> 5;
    const int lane = t & 31;

    const float4 th0 = *reinterpret_cast<const float4*>(theta + 4 * t);
    const float4 th1 = *reinterpret_cast<const float4*>(theta + 1024 + 4 * t);

    float4 acc0 = make_float4(0.f, 0.f, 0.f, 0.f);
    float4 acc1 = make_float4(0.f, 0.f, 0.f, 0.f);

    const int first = blockIdx.x * RPS;
    const int nst   = (N_ROWS - first + SWEEP - 1) / SWEEP;   // 18 or 19

    if (t == 0) {
        #pragma unroll
        for (int i = 0; i < NSTAGE; i++)
            mbar_init(smem_u32(&mbar_full[i]), 1);
    }
    __syncthreads();

    auto issue = [&](int s) {
        const int slot = s % NSTAGE;
        const uint32_t mbar = smem_u32(&mbar_full[slot]);
        const uint32_t dst0 = smem_u32(buf + slot * STAGE_FLOATS);
        const int base = first + s * SWEEP;
        mbar_expect_tx(mbar, STAGE_BYTES);
        #pragma unroll
        for (int j = 0; j < RPS; j++) {
            int rj = base + j;
            if (rj > N_ROWS - 1) rj = N_ROWS - 1;   // clamp; c forced to 0 later
            bulk_copy(dst0 + j * ROW_BYTES, xs + (size_t)rj * D, ROW_BYTES, mbar);
        }
    };

    if (t == 0) {
        #pragma unroll
        for (int s = 0; s < NSTAGE; s++)
            if (s < nst) issue(s);
    }

    for (int s = 0; s < nst; s++) {
        const int slot = s % NSTAGE;
        mbar_wait(smem_u32(&mbar_full[slot]), (uint32_t)((s / NSTAGE) & 1));

        const float* src = buf + slot * STAGE_FLOATS;
        float4 a[RPS][2];
        float  sm[RPS];

        #pragma unroll
        for (int j = 0; j < RPS; j++) {
            a[j][0] = *reinterpret_cast<const float4*>(src + j * D + 4 * t);
            a[j][1] = *reinterpret_cast<const float4*>(src + j * D + 1024 + 4 * t);
            sm[j] = a[j][0].x * th0.x + a[j][0].y * th0.y
                  + a[j][0].z * th0.z + a[j][0].w * th0.w
                  + a[j][1].x * th1.x + a[j][1].y * th1.y
                  + a[j][1].z * th1.z + a[j][1].w * th1.w;
        }

        #pragma unroll
        for (int o = 16; o > 0; o >>= 1) {
            #pragma unroll
            for (int j = 0; j < RPS; j++)
                sm[j] += __shfl_down_sync(0xffffffffu, sm[j], o);
        }
        if (lane == 0) {
            #pragma unroll
            for (int j = 0; j < RPS; j++)
                s_dot[wid][j] = sm[j];
        }
        __syncthreads();

        if (t < RPS) {
            float v = s_dot[0][t];
            #pragma unroll
            for (int w = 1; w < 8; w++) v += s_dot[w][t];
            const int rj = first + s * SWEEP + t;
            s_c[t] = (rj < N_ROWS) ? (ETA / (1.0f + __expf(v))) : 0.f;
        }
        __syncthreads();

        #pragma unroll
        for (int j = 0; j < RPS; j++) {
            const float c = s_c[j];
            acc0.x += c * a[j][0].x;  acc0.y += c * a[j][0].y;
            acc0.z += c * a[j][0].z;  acc0.w += c * a[j][0].w;
            acc1.x += c * a[j][1].x;  acc1.y += c * a[j][1].y;
            acc1.z += c * a[j][1].z;  acc1.w += c * a[j][1].w;
        }
        __syncthreads();   // all reads of buf[slot] + s_dot/s_c done

        const int sn = s + NSTAGE;
        if (sn < nst && t == 0) issue(sn);   // LATE refill (R12 placement)
    }

    float* part = g_partial[blockIdx.x];
    *reinterpret_cast<float4*>(part + 4 * t)        = acc0;
    *reinterpret_cast<float4*>(part + 1024 + 4 * t) = acc1;
}

// Fused reduction: 148 partials + theta -> out. grid 16 x 512 (R11 shape).
__global__ __launch_bounds__(512)
void pass2_kernel(const float* __restrict__ theta,
                  float* __restrict__ out)
{
    __shared__ float4 s_red[16][32];

    const int lane32 = threadIdx.x & 31;
    const int grp    = threadIdx.x >> 5;
    const int col4   = blockIdx.x * 32 + lane32;

    // 148 = 4*10 + 12*9: grp < 4 have 10 rows, others 9.
    const int start = grp * 9 + (grp < 4 ? grp : 4);
    const int count = 9 + (grp < 4 ? 1 : 0);

    float4 acc[5];
    #pragma unroll
    for (int k = 0; k < 5; k++) acc[k] = make_float4(0.f, 0.f, 0.f, 0.f);

    #pragma unroll 5
    for (int k = 0; k < 5; k++) {
        const float4 v = reinterpret_cast<const float4*>(g_partial[start + k])[col4];
        acc[k].x += v.x; acc[k].y += v.y; acc[k].z += v.z; acc[k].w += v.w;
    }
    #pragma unroll 5
    for (int k = 0; k < 5; k++) {
        if (5 + k < count) {
            const float4 v = reinterpret_cast<const float4*>(g_partial[start + 5 + k])[col4];
            acc[k].x += v.x; acc[k].y += v.y; acc[k].z += v.z; acc[k].w += v.w;
        }
    }

    float4 s;
    s.x = ((acc[0].x + acc[1].x) + (acc[2].x + acc[3].x)) + acc[4].x;
    s.y = ((acc[0].y + acc[1].y) + (acc[2].y + acc[3].y)) + acc[4].y;
    s.z = ((acc[0].z + acc[1].z) + (acc[2].z + acc[3].z)) + acc[4].z;
    s.w = ((acc[0].w + acc[1].w) + (acc[2].w + acc[3].w)) + acc[4].w;

    s_red[grp][lane32] = s;
    __syncthreads();

    if (grp == 0) {
        const float4 th = reinterpret_cast<const float4*>(theta)[col4];
        float4 r = th;
        #pragma unroll
        for (int g = 0; g < 16; g++) {
            const float4 v = s_red[g][lane32];
            r.x += v.x; r.y += v.y; r.z += v.z; r.w += v.w;
        }
        reinterpret_cast<float4*>(out)[col4] = r;
    }
}

extern "C" void kernel_launch(void* const* d_in, const int* in_sizes, int n_in,
                              void* d_out, int out_size)
{
    const float* theta = (const float*)d_in[0];
    const float* xs    = (const float*)d_in[1];
    if (n_in >= 2 && in_sizes[0] > in_sizes[1]) {
        theta = (const float*)d_in[1];
        xs    = (const float*)d_in[0];
    }
    float* out = (float*)d_out;

    const int smem = NSTAGE * STAGE_BYTES;   // 196608
    cudaFuncSetAttribute(pass1_kernel,
                         cudaFuncAttributeMaxDynamicSharedMemorySize, smem);

    pass1_kernel<<<GRID1, THREADS, smem>>>(theta, xs);
    pass2_kernel<<<16, 512>>>(theta, out);
}